// round 1
// baseline (speedup 1.0000x reference)
#include <cuda_runtime.h>
#include <math.h>

#define T_TOK 8192
#define D_IN  1024
#define DFF   4096
#define NE    8

// ---------------- device scratch (static: no allocations allowed) ----------
__device__ int   g_count[NE];
__device__ int   g_slot[NE * T_TOK];     // token ids bucketed per expert
__device__ float g_scale[T_TOK];         // router prob of selected expert
__device__ float g_h[(size_t)T_TOK * DFF]; // 134 MB intermediate, token-indexed

// ---------------- kernel 0: zero counters ----------------------------------
__global__ void zero_counts_k() {
    if (threadIdx.x < NE) g_count[threadIdx.x] = 0;
}

// ---------------- kernel 1: router (1 warp / token) -------------------------
// logits = x[t] @ gate_w  -> softmax -> argmax expert + its prob.
// Double accumulation to keep argmax decisions as close to exact as possible.
__global__ void router_k(const float* __restrict__ x, const float* __restrict__ gw) {
    int warp = (blockIdx.x * blockDim.x + threadIdx.x) >> 5;
    int lane = threadIdx.x & 31;
    if (warp >= T_TOK) return;
    const float* xr = x + (size_t)warp * D_IN;

    double acc[NE];
#pragma unroll
    for (int j = 0; j < NE; j++) acc[j] = 0.0;

    for (int d = lane; d < D_IN; d += 32) {
        float xv = xr[d];
        const float4* g4 = reinterpret_cast<const float4*>(gw + d * NE);
        float4 a = g4[0], b = g4[1];
        acc[0] += (double)xv * a.x; acc[1] += (double)xv * a.y;
        acc[2] += (double)xv * a.z; acc[3] += (double)xv * a.w;
        acc[4] += (double)xv * b.x; acc[5] += (double)xv * b.y;
        acc[6] += (double)xv * b.z; acc[7] += (double)xv * b.w;
    }
#pragma unroll
    for (int j = 0; j < NE; j++)
#pragma unroll
        for (int s = 16; s > 0; s >>= 1)
            acc[j] += __shfl_xor_sync(0xffffffffu, acc[j], s);

    if (lane == 0) {
        double m = acc[0]; int am = 0;
#pragma unroll
        for (int j = 1; j < NE; j++) if (acc[j] > m) { m = acc[j]; am = j; }
        double s = 0.0;
#pragma unroll
        for (int j = 0; j < NE; j++) s += exp(acc[j] - m);
        g_scale[warp] = (float)(1.0 / s);       // prob of argmax expert
        int pos = atomicAdd(&g_count[am], 1);
        g_slot[am * T_TOK + pos] = warp;
    }
}

// ---------------- grouped SGEMM: 128x128 tile, BK=8, 8x8/thread -------------
// DO_GELU=true : Out = g_h, C = gelu(A@w1[e] + b1[e]),   A = x       (K=1024,N=4096)
// DO_GELU=false: Out = out, C = scale * (g_h@w2[e]+b2[e]), A = g_h   (K=4096,N=1024)
__device__ __forceinline__ float gelu_exact(float v) {
    return 0.5f * v * (1.0f + erff(v * 0.70710678118654752f));
}

template <bool DO_GELU>
__global__ __launch_bounds__(256)
void moe_gemm_k(const float* __restrict__ A_in,   // token-indexed [T, K]
                const float* __restrict__ W,      // [NE, K, N]
                const float* __restrict__ Bias,   // [NE, N]
                float* __restrict__ Out_in,       // token-indexed [T, N] (gemm2)
                int K, int N) {
    const int e  = blockIdx.z;
    const int Me = g_count[e];
    const int m0 = blockIdx.y * 128;
    if (m0 >= Me) return;
    const int n0 = blockIdx.x * 128;

    const float* A   = DO_GELU ? A_in : g_h;
    float*       Out = DO_GELU ? g_h  : Out_in;

    __shared__ float As[8][128];
    __shared__ float Bs[8][128];
    __shared__ int   toks[128];

    const int tid = threadIdx.x;
    if (tid < 128) {
        int p = m0 + tid;
        toks[tid] = (p < Me) ? g_slot[e * T_TOK + p] : -1;
    }
    __syncthreads();

    // A-load mapping: 128 rows x 8 k, float4 per thread
    const int ar  = tid >> 1;
    const int ak4 = (tid & 1) * 4;
    const int tokA = toks[ar];
    const float* aptr = (tokA >= 0) ? (A + (size_t)tokA * K + ak4) : nullptr;
    // B-load mapping: 8 k x 128 n, float4 per thread
    const int bk  = tid >> 5;
    const int bn  = (tid & 31) * 4;
    const float* bptr = W + ((size_t)e * K + bk) * N + n0 + bn;

    const int tr = tid >> 4;   // 0..15 -> rows tr*8..tr*8+7
    const int tc = tid & 15;   // 0..15 -> cols tc*8..tc*8+7

    float acc[8][8];
#pragma unroll
    for (int i = 0; i < 8; i++)
#pragma unroll
        for (int j = 0; j < 8; j++) acc[i][j] = 0.f;

    for (int k0 = 0; k0 < K; k0 += 8) {
        float4 av = make_float4(0.f, 0.f, 0.f, 0.f);
        if (aptr) av = *reinterpret_cast<const float4*>(aptr + k0);
        float4 bv = *reinterpret_cast<const float4*>(bptr + (size_t)k0 * N);
        As[ak4 + 0][ar] = av.x;
        As[ak4 + 1][ar] = av.y;
        As[ak4 + 2][ar] = av.z;
        As[ak4 + 3][ar] = av.w;
        *reinterpret_cast<float4*>(&Bs[bk][bn]) = bv;
        __syncthreads();

#pragma unroll
        for (int kk = 0; kk < 8; kk++) {
            float4 a0 = *reinterpret_cast<const float4*>(&As[kk][tr * 8]);
            float4 a1 = *reinterpret_cast<const float4*>(&As[kk][tr * 8 + 4]);
            float4 b0 = *reinterpret_cast<const float4*>(&Bs[kk][tc * 8]);
            float4 b1 = *reinterpret_cast<const float4*>(&Bs[kk][tc * 8 + 4]);
            float a[8] = {a0.x, a0.y, a0.z, a0.w, a1.x, a1.y, a1.z, a1.w};
            float b[8] = {b0.x, b0.y, b0.z, b0.w, b1.x, b1.y, b1.z, b1.w};
#pragma unroll
            for (int i = 0; i < 8; i++)
#pragma unroll
                for (int j = 0; j < 8; j++) acc[i][j] += a[i] * b[j];
        }
        __syncthreads();
    }

    // epilogue
    const float* brow = Bias + (size_t)e * N + n0 + tc * 8;
    float bia[8];
#pragma unroll
    for (int j = 0; j < 8; j++) bia[j] = brow[j];

#pragma unroll
    for (int i = 0; i < 8; i++) {
        int tk = toks[tr * 8 + i];
        if (tk < 0) continue;
        float sc = DO_GELU ? 1.f : g_scale[tk];
        float v[8];
#pragma unroll
        for (int j = 0; j < 8; j++) {
            float t = acc[i][j] + bia[j];
            v[j] = DO_GELU ? gelu_exact(t) : t * sc;
        }
        float* orow = Out + (size_t)tk * N + n0 + tc * 8;
        *reinterpret_cast<float4*>(orow)     = make_float4(v[0], v[1], v[2], v[3]);
        *reinterpret_cast<float4*>(orow + 4) = make_float4(v[4], v[5], v[6], v[7]);
    }
}

// ---------------- launch ----------------------------------------------------
extern "C" void kernel_launch(void* const* d_in, const int* in_sizes, int n_in,
                              void* d_out, int out_size) {
    const float* x  = (const float*)d_in[0];
    const float* gw = (const float*)d_in[1];
    const float* w1 = (const float*)d_in[2];
    const float* b1 = (const float*)d_in[3];
    const float* w2 = (const float*)d_in[4];
    const float* b2 = (const float*)d_in[5];
    float* out = (float*)d_out;

    zero_counts_k<<<1, 32>>>();
    router_k<<<(T_TOK * 32) / 256, 256>>>(x, gw);

    dim3 g1(DFF / 128, T_TOK / 128, NE);   // (32, 64, 8) — empty m-tiles early-exit
    moe_gemm_k<true><<<g1, 256>>>(x, w1, b1, nullptr, D_IN, DFF);

    dim3 g2(D_IN / 128, T_TOK / 128, NE);  // (8, 64, 8)
    moe_gemm_k<false><<<g2, 256>>>(nullptr, w2, b2, out, DFF, D_IN);
}

// round 3
// speedup vs baseline: 1.8722x; 1.8722x over previous
#include <cuda_runtime.h>
#include <cuda_bf16.h>
#include <mma.h>
#include <math.h>
#include <cstdint>

using namespace nvcuda;

#define T_TOK 8192
#define D_IN  1024
#define DFF   4096
#define NE    8

// ---------------- device scratch (static: no allocations allowed) ----------
__device__ int   g_count[NE];
__device__ int   g_slot[NE * T_TOK];       // token ids bucketed per expert
__device__ float g_scale[T_TOK];           // router prob of selected expert
__device__ float g_h[(size_t)T_TOK * DFF]; // 134 MB fp32 intermediate

// ---------------- kernel 0: zero counters ----------------------------------
__global__ void zero_counts_k() {
    if (threadIdx.x < NE) g_count[threadIdx.x] = 0;
}

// ---------------- kernel 1: router (1 warp / token) -------------------------
__global__ void router_k(const float* __restrict__ x, const float* __restrict__ gw) {
    int warp = (blockIdx.x * blockDim.x + threadIdx.x) >> 5;
    int lane = threadIdx.x & 31;
    if (warp >= T_TOK) return;
    const float* xr = x + (size_t)warp * D_IN;

    double acc[NE];
#pragma unroll
    for (int j = 0; j < NE; j++) acc[j] = 0.0;

    for (int d = lane; d < D_IN; d += 32) {
        float xv = xr[d];
        const float4* g4 = reinterpret_cast<const float4*>(gw + d * NE);
        float4 a = g4[0], b = g4[1];
        acc[0] += (double)xv * a.x; acc[1] += (double)xv * a.y;
        acc[2] += (double)xv * a.z; acc[3] += (double)xv * a.w;
        acc[4] += (double)xv * b.x; acc[5] += (double)xv * b.y;
        acc[6] += (double)xv * b.z; acc[7] += (double)xv * b.w;
    }
#pragma unroll
    for (int j = 0; j < NE; j++)
#pragma unroll
        for (int s = 16; s > 0; s >>= 1)
            acc[j] += __shfl_xor_sync(0xffffffffu, acc[j], s);

    if (lane == 0) {
        double m = acc[0]; int am = 0;
#pragma unroll
        for (int j = 1; j < NE; j++) if (acc[j] > m) { m = acc[j]; am = j; }
        double s = 0.0;
#pragma unroll
        for (int j = 0; j < NE; j++) s += exp(acc[j] - m);
        g_scale[warp] = (float)(1.0 / s);
        int pos = atomicAdd(&g_count[am], 1);
        g_slot[am * T_TOK + pos] = warp;
    }
}

// ---------------- helpers ---------------------------------------------------
__device__ __forceinline__ float gelu_exact(float v) {
    return 0.5f * v * (1.0f + erff(v * 0.70710678118654752f));
}

__device__ __forceinline__ unsigned int pack_bf2(float a, float b) {
    __nv_bfloat162 t = __floats2bfloat162_rn(a, b);
    return reinterpret_cast<unsigned int&>(t);
}

// Convert 8 fp32 -> 8 bf16 hi + 8 bf16 lo, store 16B each.
__device__ __forceinline__ void cvt_store8(__nv_bfloat16* hi, __nv_bfloat16* lo,
                                           float4 x, float4 y) {
    float f[8] = {x.x, x.y, x.z, x.w, y.x, y.y, y.z, y.w};
    float l[8];
#pragma unroll
    for (int q = 0; q < 8; q++) {
        float h = __bfloat162float(__float2bfloat16_rn(f[q]));
        l[q] = f[q] - h;
    }
    uint4 hp, lp;
    hp.x = pack_bf2(f[0], f[1]); hp.y = pack_bf2(f[2], f[3]);
    hp.z = pack_bf2(f[4], f[5]); hp.w = pack_bf2(f[6], f[7]);
    lp.x = pack_bf2(l[0], l[1]); lp.y = pack_bf2(l[2], l[3]);
    lp.z = pack_bf2(l[4], l[5]); lp.w = pack_bf2(l[6], l[7]);
    *reinterpret_cast<uint4*>(hi) = hp;
    *reinterpret_cast<uint4*>(lo) = lp;
}

// ---------------- grouped GEMM via wmma bf16 3-split ------------------------
// DO_GELU=true : g_h = gelu(x @ w1[e] + b1[e]),          K=1024, N=4096
// DO_GELU=false: out = scale * (g_h @ w2[e] + b2[e]),    K=4096, N=1024
// Block tile 128x128, k-step 16, 8 warps (2 M x 4 N), warp tile 64x32.
template <bool DO_GELU>
__global__ __launch_bounds__(256)
void moe_gemm_tc(const float* __restrict__ A_in,   // token-indexed [T, K] fp32
                 const float* __restrict__ W,      // [NE, K, N] fp32
                 const float* __restrict__ Bias,   // [NE, N] fp32
                 float* __restrict__ Out_in,       // token-indexed [T, N] fp32
                 int K, int N) {
    const int e  = blockIdx.z;
    const int Me = g_count[e];
    const int m0 = blockIdx.y * 128;
    if (m0 >= Me) return;
    const int n0 = blockIdx.x * 128;

    const float* A   = DO_GELU ? A_in : g_h;
    float*       Out = DO_GELU ? g_h  : Out_in;

    __shared__ __align__(16) __nv_bfloat16 As_hi[128][24];
    __shared__ __align__(16) __nv_bfloat16 As_lo[128][24];
    __shared__ __align__(16) __nv_bfloat16 Bs_hi[16][136];
    __shared__ __align__(16) __nv_bfloat16 Bs_lo[16][136];
    __shared__ float eps[8][16][20];
    __shared__ int   toks[128];

    const int tid = threadIdx.x;
    if (tid < 128) {
        int p = m0 + tid;
        toks[tid] = (p < Me) ? g_slot[e * T_TOK + p] : -1;
    }
    __syncthreads();

    // A-load mapping: 128 rows x 16 k fp32; thread -> (row, 8-col chunk)
    const int ar = tid >> 1;
    const int ac = (tid & 1) * 8;
    const int tokA = toks[ar];
    const float* aptr = (tokA >= 0) ? (A + (size_t)tokA * K + ac) : nullptr;
    // B-load mapping: 16 k x 128 n fp32; thread -> (k-row, 8-col chunk)
    const int br = tid >> 4;
    const int bc = (tid & 15) * 8;
    const float* bptr = W + ((size_t)e * K + br) * N + n0 + bc;

    const int wid = tid >> 5;
    const int lane = tid & 31;
    const int wm = wid & 1;    // 0..1 -> rows wm*64..+64
    const int wn = wid >> 1;   // 0..3 -> cols wn*32..+32

    wmma::fragment<wmma::accumulator, 16, 16, 16, float> acc[4][2];
#pragma unroll
    for (int i = 0; i < 4; i++)
#pragma unroll
        for (int j = 0; j < 2; j++) wmma::fill_fragment(acc[i][j], 0.0f);

    // prefetch k0 = 0
    float4 pa0 = make_float4(0.f, 0.f, 0.f, 0.f), pa1 = pa0;
    if (aptr) {
        pa0 = *reinterpret_cast<const float4*>(aptr);
        pa1 = *reinterpret_cast<const float4*>(aptr + 4);
    }
    float4 pb0 = *reinterpret_cast<const float4*>(bptr);
    float4 pb1 = *reinterpret_cast<const float4*>(bptr + 4);

    for (int k0 = 0; k0 < K; k0 += 16) {
        cvt_store8(&As_hi[ar][ac], &As_lo[ar][ac], pa0, pa1);
        cvt_store8(&Bs_hi[br][bc], &Bs_lo[br][bc], pb0, pb1);
        __syncthreads();

        int k1 = k0 + 16;
        if (k1 < K) {
            if (aptr) {
                pa0 = *reinterpret_cast<const float4*>(aptr + k1);
                pa1 = *reinterpret_cast<const float4*>(aptr + k1 + 4);
            }
            pb0 = *reinterpret_cast<const float4*>(bptr + (size_t)k1 * N);
            pb1 = *reinterpret_cast<const float4*>(bptr + (size_t)k1 * N + 4);
        }

        wmma::fragment<wmma::matrix_a, 16, 16, 16, __nv_bfloat16, wmma::row_major> ah[4], al[4];
        wmma::fragment<wmma::matrix_b, 16, 16, 16, __nv_bfloat16, wmma::row_major> bh[2], bl[2];
#pragma unroll
        for (int i = 0; i < 4; i++) {
            wmma::load_matrix_sync(ah[i], &As_hi[wm * 64 + i * 16][0], 24);
            wmma::load_matrix_sync(al[i], &As_lo[wm * 64 + i * 16][0], 24);
        }
#pragma unroll
        for (int j = 0; j < 2; j++) {
            wmma::load_matrix_sync(bh[j], &Bs_hi[0][wn * 32 + j * 16], 136);
            wmma::load_matrix_sync(bl[j], &Bs_lo[0][wn * 32 + j * 16], 136);
        }
#pragma unroll
        for (int i = 0; i < 4; i++)
#pragma unroll
            for (int j = 0; j < 2; j++) {
                wmma::mma_sync(acc[i][j], ah[i], bh[j], acc[i][j]);
                wmma::mma_sync(acc[i][j], ah[i], bl[j], acc[i][j]);
                wmma::mma_sync(acc[i][j], al[i], bh[j], acc[i][j]);
            }
        __syncthreads();
    }

    // ---------------- epilogue ----------------
    const int r  = lane >> 1;
    const int c8 = (lane & 1) * 8;
#pragma unroll
    for (int i = 0; i < 4; i++) {
        const int lrow = wm * 64 + i * 16 + r;
        const int tok  = toks[lrow];
#pragma unroll
        for (int j = 0; j < 2; j++) {
            wmma::store_matrix_sync(&eps[wid][0][0], acc[i][j], 20, wmma::mem_row_major);
            __syncwarp();
            if (tok >= 0) {
                const int col = n0 + wn * 32 + j * 16 + c8;
                const float* bb = Bias + (size_t)e * N + col;
                float sc = DO_GELU ? 1.0f : g_scale[tok];
                float v[8];
#pragma unroll
                for (int q = 0; q < 8; q++) {
                    float t = eps[wid][r][c8 + q] + bb[q];
                    v[q] = DO_GELU ? gelu_exact(t) : t * sc;
                }
                float* orow = Out + (size_t)tok * N + col;
                *reinterpret_cast<float4*>(orow)     = make_float4(v[0], v[1], v[2], v[3]);
                *reinterpret_cast<float4*>(orow + 4) = make_float4(v[4], v[5], v[6], v[7]);
            }
            __syncwarp();
        }
    }
}

// ---------------- launch ----------------------------------------------------
extern "C" void kernel_launch(void* const* d_in, const int* in_sizes, int n_in,
                              void* d_out, int out_size) {
    const float* x  = (const float*)d_in[0];
    const float* gw = (const float*)d_in[1];
    const float* w1 = (const float*)d_in[2];
    const float* b1 = (const float*)d_in[3];
    const float* w2 = (const float*)d_in[4];
    const float* b2 = (const float*)d_in[5];
    float* out = (float*)d_out;

    zero_counts_k<<<1, 32>>>();
    router_k<<<(T_TOK * 32) / 256, 256>>>(x, gw);

    dim3 g1(DFF / 128, T_TOK / 128, NE);   // (32, 64, 8) — empty m-tiles early-exit
    moe_gemm_tc<true><<<g1, 256>>>(x, w1, b1, nullptr, D_IN, DFF);

    dim3 g2(D_IN / 128, T_TOK / 128, NE);  // (8, 64, 8)
    moe_gemm_tc<false><<<g2, 256>>>(nullptr, w2, b2, out, DFF, D_IN);
}

// round 7
// speedup vs baseline: 2.0638x; 1.1024x over previous
#include <cuda_runtime.h>
#include <cuda_bf16.h>
#include <math.h>
#include <cstdint>
#include <cstddef>

#define T_TOK 8192
#define D_IN  1024
#define DFF   4096
#define NE    8

// ---------------- device scratch (proven R3 layout) ----------------
__device__ int   g_count[NE];
__device__ int   g_slot[NE * T_TOK];                    // token ids bucketed per expert
__device__ float g_scale[T_TOK];                        // router prob of selected expert
__device__ __align__(16) float g_h[(size_t)T_TOK * DFF]; // fp32 intermediate, token-indexed

// ---------------- PTX helpers ----------------
__device__ __forceinline__ unsigned smem_u32(const void* p) {
    unsigned a;
    asm("{ .reg .u64 t; cvta.to.shared.u64 t, %1; cvt.u32.u64 %0, t; }" : "=r"(a) : "l"(p));
    return a;
}
#define LDSM_X4(r, a) \
    asm volatile("ldmatrix.sync.aligned.m8n8.x4.shared.b16 {%0,%1,%2,%3}, [%4];" \
        : "=r"((r)[0]), "=r"((r)[1]), "=r"((r)[2]), "=r"((r)[3]) : "r"(a))
#define LDSM_X4_T(r, a) \
    asm volatile("ldmatrix.sync.aligned.m8n8.x4.trans.shared.b16 {%0,%1,%2,%3}, [%4];" \
        : "=r"((r)[0]), "=r"((r)[1]), "=r"((r)[2]), "=r"((r)[3]) : "r"(a))
#define MMA_BF16(d, a, b0, b1) \
    asm volatile("mma.sync.aligned.m16n8k16.row.col.f32.bf16.bf16.f32 " \
        "{%0,%1,%2,%3}, {%4,%5,%6,%7}, {%8,%9}, {%0,%1,%2,%3};" \
        : "+f"((d)[0]), "+f"((d)[1]), "+f"((d)[2]), "+f"((d)[3]) \
        : "r"((a)[0]), "r"((a)[1]), "r"((a)[2]), "r"((a)[3]), "r"(b0), "r"(b1))

// ---------------- misc helpers ----------------
__device__ __forceinline__ float gelu_exact(float v) {
    return 0.5f * v * (1.0f + erff(v * 0.70710678118654752f));
}
__device__ __forceinline__ unsigned pack_bf2(float a, float b) {
    __nv_bfloat162 t = __floats2bfloat162_rn(a, b);
    return reinterpret_cast<unsigned&>(t);
}
// Convert 8 fp32 -> hi/lo bf16 chunks (16B each) at given smem byte addresses.
__device__ __forceinline__ void cvt_store8(unsigned char* hi, unsigned char* lo,
                                           float4 x, float4 y) {
    float f[8] = {x.x, x.y, x.z, x.w, y.x, y.y, y.z, y.w};
    float l[8];
#pragma unroll
    for (int q = 0; q < 8; q++) {
        float h = __bfloat162float(__float2bfloat16_rn(f[q]));
        l[q] = f[q] - h;
    }
    uint4 hp = make_uint4(pack_bf2(f[0], f[1]), pack_bf2(f[2], f[3]),
                          pack_bf2(f[4], f[5]), pack_bf2(f[6], f[7]));
    uint4 lp = make_uint4(pack_bf2(l[0], l[1]), pack_bf2(l[2], l[3]),
                          pack_bf2(l[4], l[5]), pack_bf2(l[6], l[7]));
    *reinterpret_cast<uint4*>(hi) = hp;
    *reinterpret_cast<uint4*>(lo) = lp;
}

// ---------------- kernel 0: zero counters ----------------
__global__ void zero_counts_k() { if (threadIdx.x < NE) g_count[threadIdx.x] = 0; }

// ---------------- kernel 1: router (1 warp / token, proven) ----------------
__global__ void router_k(const float* __restrict__ x, const float* __restrict__ gw) {
    int warp = (blockIdx.x * blockDim.x + threadIdx.x) >> 5;
    int lane = threadIdx.x & 31;
    if (warp >= T_TOK) return;
    const float* xr = x + (size_t)warp * D_IN;
    double acc[NE];
#pragma unroll
    for (int j = 0; j < NE; j++) acc[j] = 0.0;
    for (int d = lane; d < D_IN; d += 32) {
        float xv = xr[d];
        const float4* g4 = reinterpret_cast<const float4*>(gw + d * NE);
        float4 a = g4[0], b = g4[1];
        acc[0] += (double)xv * a.x; acc[1] += (double)xv * a.y;
        acc[2] += (double)xv * a.z; acc[3] += (double)xv * a.w;
        acc[4] += (double)xv * b.x; acc[5] += (double)xv * b.y;
        acc[6] += (double)xv * b.z; acc[7] += (double)xv * b.w;
    }
#pragma unroll
    for (int j = 0; j < NE; j++)
#pragma unroll
        for (int s = 16; s > 0; s >>= 1)
            acc[j] += __shfl_xor_sync(0xffffffffu, acc[j], s);
    if (lane == 0) {
        double m = acc[0]; int am = 0;
#pragma unroll
        for (int j = 1; j < NE; j++) if (acc[j] > m) { m = acc[j]; am = j; }
        double s = 0.0;
#pragma unroll
        for (int j = 0; j < NE; j++) s += exp(acc[j] - m);
        g_scale[warp] = (float)(1.0 / s);
        int pos = atomicAdd(&g_count[am], 1);
        g_slot[am * T_TOK + pos] = warp;
    }
}

// ---------------- grouped GEMM: raw mma + ldmatrix, R3 plumbing -------------
// Block 128x128, k-step 16. 8 warps: wm = wid&1 (64 m-rows), wn = wid>>1 (32 n-cols).
// smem: Ahi[128][16] | Alo | Bhi[16][128] | Blo, bf16, 4 KB each (16 KB total).
// A swizzle: 16B chunk c (k-half) stored at c ^ ((row>>2)&1).
// B swizzle: 16B n-chunk nc (of 16) stored at nc ^ (krow&7).
template <bool DO_GELU>
__global__ __launch_bounds__(256)
void moe_mma(const float* __restrict__ A_in,   // token-indexed [T, K] fp32
             const float* __restrict__ W,      // [NE, K, N] fp32 (native layout)
             const float* __restrict__ Bias,   // [NE, N] fp32
             float* __restrict__ Out_in,       // token-indexed [T, N] fp32
             int K, int N) {
    const int e  = blockIdx.z;
    const int Me = g_count[e];
    const int m0 = blockIdx.y * 128;
    if (m0 >= Me) return;
    const int n0 = blockIdx.x * 128;

    const float* A   = DO_GELU ? A_in : g_h;
    float*       Out = DO_GELU ? g_h  : Out_in;

    __shared__ __align__(16) unsigned char sm[16384];
    __shared__ int toks[128];

    const int tid = threadIdx.x;
    if (tid < 128) {
        int p = m0 + tid;
        toks[tid] = (p < Me) ? g_slot[e * T_TOK + p] : -1;
    }
    __syncthreads();

    // A staging: thread -> (row ar, k-chunk ac8 of 8 fp32)
    const int ar  = tid >> 1;
    const int ac8 = tid & 1;
    const int tokA = toks[ar];
    const float* aptr = (tokA >= 0) ? (A + (size_t)tokA * K + ac8 * 8) : nullptr;
    const unsigned aoff = (unsigned)(ar * 32 + ((ac8 ^ ((ar >> 2) & 1)) << 4));
    // B staging: thread -> (k-row bk, n-chunk bnc of 8 fp32)
    const int bk  = tid >> 4;
    const int bnc = tid & 15;
    const float* bptr = W + ((size_t)e * K + bk) * N + n0 + bnc * 8;
    const unsigned boff = (unsigned)(bk * 256 + ((bnc ^ (bk & 7)) << 4));

    const int wid = tid >> 5, lane = tid & 31;
    const int wm = wid & 1, wn = wid >> 1;
    const int lane4 = lane & 15, laneh = lane >> 4;
    // A fragment base: rows wm*64 + lane4 (+ mi*16), k-chunk laneh
    const unsigned offA = (unsigned)((wm * 64 + lane4) * 32 + ((laneh ^ ((lane4 >> 2) & 1)) << 4));
    // B fragment addressing (ldmatrix.trans on [k][n] tile):
    // lanes 0-7: (k0-7, ngrp0) | 8-15: (k0-7, ngrp1) | 16-23: (k8-15, ngrp0) | 24-31: (k8-15, ngrp1)
    const int khalf = (lane >> 4) & 1, ngrp = (lane >> 3) & 1, tt = lane & 7;
    const int krow = khalf * 8 + tt;
    const unsigned offB0 = (unsigned)(8192 + krow * 256 + (((wn * 4 + ngrp)     ^ (krow & 7)) << 4));
    const unsigned offB1 = (unsigned)(8192 + krow * 256 + (((wn * 4 + 2 + ngrp) ^ (krow & 7)) << 4));
    const unsigned base = smem_u32(sm);

    float acc[4][4][4];
#pragma unroll
    for (int i = 0; i < 4; i++)
#pragma unroll
        for (int j = 0; j < 4; j++)
#pragma unroll
            for (int q = 0; q < 4; q++) acc[i][j][q] = 0.0f;

    // prefetch k0 = 0 (R3-proven pattern)
    float4 pa0 = make_float4(0.f, 0.f, 0.f, 0.f), pa1 = pa0;
    if (aptr) {
        pa0 = *reinterpret_cast<const float4*>(aptr);
        pa1 = *reinterpret_cast<const float4*>(aptr + 4);
    }
    float4 pb0 = *reinterpret_cast<const float4*>(bptr);
    float4 pb1 = *reinterpret_cast<const float4*>(bptr + 4);

    for (int k0 = 0; k0 < K; k0 += 16) {
        cvt_store8(sm + aoff,        sm + 4096  + aoff, pa0, pa1);
        cvt_store8(sm + 8192 + boff, sm + 12288 + boff, pb0, pb1);
        __syncthreads();

        const int k1 = k0 + 16;
        if (k1 < K) {
            if (aptr) {
                pa0 = *reinterpret_cast<const float4*>(aptr + k1);
                pa1 = *reinterpret_cast<const float4*>(aptr + k1 + 4);
            }
            pb0 = *reinterpret_cast<const float4*>(bptr + (size_t)k1 * N);
            pb1 = *reinterpret_cast<const float4*>(bptr + (size_t)k1 * N + 4);
        }

        unsigned ah[4][4], al[4][4], bh[2][4], bl[2][4];
#pragma unroll
        for (int mi = 0; mi < 4; mi++) {
            LDSM_X4(ah[mi], base + offA + mi * 512);
            LDSM_X4(al[mi], base + 4096 + offA + mi * 512);
        }
        LDSM_X4_T(bh[0], base + offB0);
        LDSM_X4_T(bh[1], base + offB1);
        LDSM_X4_T(bl[0], base + offB0 + 4096);
        LDSM_X4_T(bl[1], base + offB1 + 4096);

#pragma unroll
        for (int mi = 0; mi < 4; mi++)
#pragma unroll
            for (int nt = 0; nt < 4; nt++) {
                const int nj = nt >> 1, sel = nt & 1;
                MMA_BF16(acc[mi][nt], ah[mi], bh[nj][sel], bh[nj][sel + 2]);
                MMA_BF16(acc[mi][nt], ah[mi], bl[nj][sel], bl[nj][sel + 2]);
                MMA_BF16(acc[mi][nt], al[mi], bh[nj][sel], bh[nj][sel + 2]);
            }
        __syncthreads();
    }

    // ---------------- epilogue (direct from acc regs) ----------------
    // acc[mi][nt]: d0=(r0,c), d1=(r0,c+1), d2=(r0+8,c), d3=(r0+8,c+1)
    // r0 = wm*64 + mi*16 + (lane>>2), c = wn*32 + nt*8 + (lane&3)*2
    float bb[4][2];
#pragma unroll
    for (int nt = 0; nt < 4; nt++) {
        const float2 bv = *reinterpret_cast<const float2*>(
            Bias + (size_t)e * N + n0 + wn * 32 + nt * 8 + (lane & 3) * 2);
        bb[nt][0] = bv.x; bb[nt][1] = bv.y;
    }

#pragma unroll
    for (int mi = 0; mi < 4; mi++) {
        const int r0 = wm * 64 + mi * 16 + (lane >> 2);
        const int t0 = toks[r0], t1 = toks[r0 + 8];
        if (DO_GELU) {
#pragma unroll
            for (int nt = 0; nt < 4; nt++) {
                const int col = n0 + wn * 32 + nt * 8 + (lane & 3) * 2;
                if (t0 >= 0) {
                    float2 v = make_float2(gelu_exact(acc[mi][nt][0] + bb[nt][0]),
                                           gelu_exact(acc[mi][nt][1] + bb[nt][1]));
                    *reinterpret_cast<float2*>(Out + (size_t)t0 * N + col) = v;
                }
                if (t1 >= 0) {
                    float2 v = make_float2(gelu_exact(acc[mi][nt][2] + bb[nt][0]),
                                           gelu_exact(acc[mi][nt][3] + bb[nt][1]));
                    *reinterpret_cast<float2*>(Out + (size_t)t1 * N + col) = v;
                }
            }
        } else {
            const float s0 = (t0 >= 0) ? g_scale[t0] : 0.0f;
            const float s1 = (t1 >= 0) ? g_scale[t1] : 0.0f;
#pragma unroll
            for (int nt = 0; nt < 4; nt++) {
                const int col = n0 + wn * 32 + nt * 8 + (lane & 3) * 2;
                if (t0 >= 0) {
                    float2 v = make_float2((acc[mi][nt][0] + bb[nt][0]) * s0,
                                           (acc[mi][nt][1] + bb[nt][1]) * s0);
                    *reinterpret_cast<float2*>(Out + (size_t)t0 * N + col) = v;
                }
                if (t1 >= 0) {
                    float2 v = make_float2((acc[mi][nt][2] + bb[nt][0]) * s1,
                                           (acc[mi][nt][3] + bb[nt][1]) * s1);
                    *reinterpret_cast<float2*>(Out + (size_t)t1 * N + col) = v;
                }
            }
        }
    }
}

// ---------------- launch ----------------
extern "C" void kernel_launch(void* const* d_in, const int* in_sizes, int n_in,
                              void* d_out, int out_size) {
    const float* x  = (const float*)d_in[0];
    const float* gw = (const float*)d_in[1];
    const float* w1 = (const float*)d_in[2];
    const float* b1 = (const float*)d_in[3];
    const float* w2 = (const float*)d_in[4];
    const float* b2 = (const float*)d_in[5];
    float* out = (float*)d_out;

    zero_counts_k<<<1, 32>>>();
    router_k<<<(T_TOK * 32) / 256, 256>>>(x, gw);

    dim3 g1(DFF / 128, T_TOK / 128, NE);   // (32, 64, 8) — empty m-tiles early-exit
    moe_mma<true><<<g1, 256>>>(x, w1, b1, nullptr, D_IN, DFF);

    dim3 g2(D_IN / 128, T_TOK / 128, NE);  // (8, 64, 8)
    moe_mma<false><<<g2, 256>>>(nullptr, w2, b2, out, DFF, D_IN);
}